// round 17
// baseline (speedup 1.0000x reference)
#include <cuda_runtime.h>
#include <cstdint>

#define N_NODES 100000
#define D_IN    512
#define D_H     128
#define NH      (N_NODES * D_H)
#define N_EDGES 1600000

__device__ __align__(16) float g_h[NH];
__device__ __align__(16) uint2 g_Wf[64 * 16 * 32];  // W in tf32 fragment order
__device__ double g_sum[D_H];
__device__ double g_sumsq[D_H];
__device__ float  g_scale[D_H];
__device__ float  g_shift[D_H];

__host__ __device__ __forceinline__ void tf2x32(unsigned k0, unsigned k1,
                                                unsigned &x0, unsigned &x1) {
  unsigned k2 = k0 ^ k1 ^ 0x1BD11BDAu;
  x0 += k0; x1 += k1;
#define TFR(r) { x0 += x1; x1 = (x1 << (r)) | (x1 >> (32 - (r))); x1 ^= x0; }
  TFR(13) TFR(15) TFR(26) TFR(6)   x0 += k1; x1 += k2 + 1u;
  TFR(17) TFR(29) TFR(16) TFR(24)  x0 += k2; x1 += k0 + 2u;
  TFR(13) TFR(15) TFR(26) TFR(6)   x0 += k0; x1 += k1 + 3u;
  TFR(17) TFR(29) TFR(16) TFR(24)  x0 += k1; x1 += k2 + 4u;
  TFR(13) TFR(15) TFR(26) TFR(6)   x0 += k2; x1 += k0 + 5u;
#undef TFR
}

__device__ __forceinline__ unsigned rbits32(unsigned k0, unsigned k1, unsigned i) {
  unsigned x0 = 0u, x1 = i;
  tf2x32(k0, k1, x0, x1);
  return x0 ^ x1;
}

__device__ __forceinline__ float u01(unsigned b) {
  return __uint_as_float((b >> 9) | 0x3F800000u) - 1.0f;
}

__device__ __forceinline__ float erfinv_fast(float x) {
  float w = -__logf(fmaf(-x, x, 1.0f));
  float p;
  if (w < 5.0f) {
    w -= 2.5f;
    p = 2.81022636e-08f;
    p = fmaf(p, w, 3.43273939e-07f);
    p = fmaf(p, w, -3.5233877e-06f);
    p = fmaf(p, w, -4.39150654e-06f);
    p = fmaf(p, w, 0.00021858087f);
    p = fmaf(p, w, -0.00125372503f);
    p = fmaf(p, w, -0.00417768164f);
    p = fmaf(p, w, 0.246640727f);
    p = fmaf(p, w, 1.50140941f);
  } else {
    w = sqrtf(w) - 3.0f;
    p = -0.000200214257f;
    p = fmaf(p, w, 0.000100950558f);
    p = fmaf(p, w, 0.00134934322f);
    p = fmaf(p, w, -0.00367342844f);
    p = fmaf(p, w, 0.00573950773f);
    p = fmaf(p, w, -0.0076224613f);
    p = fmaf(p, w, 0.00943887047f);
    p = fmaf(p, w, 1.00167406f);
    p = fmaf(p, w, 2.83297682f);
  }
  return p * x;
}

__device__ __forceinline__ float normal32(unsigned b) {
  const float LO = -0.99999994f;
  float f = u01(b);
  float u = fmaxf(LO, f * 2.0f + LO);
  return 1.4142135381698608f * erfinv_fast(u);
}

__device__ __forceinline__ unsigned f2tf32(float f) {
  unsigned r;
  asm("cvt.rna.tf32.f32 %0, %1;" : "=r"(r) : "f"(f));
  return r;
}

__global__ void zero_stats_kernel() {
  g_sum[threadIdx.x] = 0.0;
  g_sumsq[threadIdx.x] = 0.0;
}

// W -> tf32 fragment order: [k8(64)][nf(16)][lane(32)]{b0,b1}
__global__ void wprep_kernel(const float* __restrict__ W) {
  int t = blockIdx.x * blockDim.x + threadIdx.x;
  if (t >= 64 * 16 * 32) return;
  int lane = t & 31, nf = (t >> 5) & 15, k8 = t >> 9;
  int k = k8 * 8 + (lane & 3);
  int n = nf * 8 + (lane >> 2);
  g_Wf[t] = make_uint2(f2tf32(W[k * D_H + n]), f2tf32(W[(k + 4) * D_H + n]));
}

// Fused RNG + tf32 MMA GEMM, no smem, no barriers.
// Warp = 16 rows x 128 N; per k8 iter the warp owns 128 A-elements.
// Dropout masks: 2 threefry hashes per element (full lanes, irreducible).
// Noise: only ~25% of elements are kept -> warp-compact the kept set via
// ballot + __fns and run ceil(K/32) full-efficiency noise passes instead of 4
// quarter-efficiency ones. Bit-exact: same counters, same hashes.
__global__ __launch_bounds__(256, 2)
void gemm_rng_kernel(const float* __restrict__ data,
                     unsigned kn0, unsigned kn1,
                     unsigned ka0, unsigned ka1,
                     unsigned kb0, unsigned kb1) {
  const int lane = threadIdx.x & 31;
  const int wid  = threadIdx.x >> 5;
  const int m0   = blockIdx.x * 128;
  const int rowbase = m0 + wid * 16;            // warp's first row
  const int r0 = rowbase + (lane >> 2);
  const int r1 = r0 + 8;
  const int q  = lane & 3;
  const bool ok0 = r0 < N_NODES;
  const bool ok1 = r1 < N_NODES;
  const float* p0 = data + (size_t)r0 * D_IN + q;
  const float* p1 = data + (size_t)r1 * D_IN + q;
  const unsigned i0 = (unsigned)r0 * D_IN + (unsigned)q;
  const unsigned i1 = (unsigned)r1 * D_IN + (unsigned)q;
  const uint2* pb = g_Wf + lane;

  float acc[16][4];
#pragma unroll
  for (int nf = 0; nf < 16; nf++)
#pragma unroll
    for (int e = 0; e < 4; e++) acc[nf][e] = 0.0f;

  for (int k8 = 0; k8 < 64; k8++) {
    const int ko = k8 * 8;
    float d[4];
    d[0] = ok0 ? p0[ko]     : 0.0f;
    d[1] = ok1 ? p1[ko]     : 0.0f;
    d[2] = ok0 ? p0[ko + 4] : 0.0f;
    d[3] = ok1 ? p1[ko + 4] : 0.0f;
    // B fragments hoisted: RNG below hides their L2 latency
    uint2 b[16];
#pragma unroll
    for (int nf = 0; nf < 16; nf++)
      b[nf] = pb[((size_t)k8 * 16 + nf) * 32];

    // element counters for my 4 slots
    unsigned idx[4] = { i0 + (unsigned)ko, i1 + (unsigned)ko,
                        i0 + (unsigned)ko + 4u, i1 + (unsigned)ko + 4u };
    const bool okv[4] = { ok0, ok1, ok0, ok1 };

    // --- dropout masks (2 hashes per element, all lanes useful) ---
    bool keep[4];
#pragma unroll
    for (int e = 0; e < 4; e++) {
      unsigned h1 = rbits32(ka0, ka1, idx[e]);
      unsigned h2 = rbits32(kb0, kb1, idx[e]);
      keep[e] = okv[e] && (((h1 | h2) & 0x80000000u) == 0u);
    }

    // --- warp-compacted noise ---
    unsigned m[4];
    int off[5];
    off[0] = 0;
#pragma unroll
    for (int e = 0; e < 4; e++) {
      m[e] = __ballot_sync(0xffffffffu, keep[e]);
      off[e + 1] = off[e] + __popc(m[e]);
    }
    const int K = off[4];
    const unsigned lml = (1u << lane) - 1u;
    int rank[4];
#pragma unroll
    for (int e = 0; e < 4; e++)
      rank[e] = off[e] + __popc(m[e] & lml);

    float noise[4] = {0.f, 0.f, 0.f, 0.f};
    const int nPass = (K + 31) >> 5;
    for (int p = 0; p < nPass; p++) {
      int j = p * 32 + lane;
      float n = 0.0f;
      if (j < K) {
        int s = (j >= off[1]) + (j >= off[2]) + (j >= off[3]);
        int srcLane = __fns(m[s], 0, (j - off[s]) + 1);
        int sr = rowbase + (srcLane >> 2) + ((s & 1) ? 8 : 0);
        unsigned si = (unsigned)sr * D_IN + (unsigned)(srcLane & 3)
                      + (unsigned)ko + ((s >= 2) ? 4u : 0u);
        n = normal32(rbits32(kn0, kn1, si));
      }
#pragma unroll
      for (int e = 0; e < 4; e++) {
        float got = __shfl_sync(0xffffffffu, n, rank[e] & 31);
        if (keep[e] && (rank[e] >> 5) == p) noise[e] = got;
      }
    }

    unsigned a[4];
#pragma unroll
    for (int e = 0; e < 4; e++)
      a[e] = keep[e] ? f2tf32((d[e] + 0.01f * noise[e]) * 4.0f) : 0u;

#pragma unroll
    for (int nf = 0; nf < 16; nf++) {
      asm volatile(
        "mma.sync.aligned.m16n8k8.row.col.f32.tf32.tf32.f32 "
        "{%0,%1,%2,%3}, {%4,%5,%6,%7}, {%8,%9}, {%0,%1,%2,%3};\n"
        : "+f"(acc[nf][0]), "+f"(acc[nf][1]),
          "+f"(acc[nf][2]), "+f"(acc[nf][3])
        : "r"(a[0]), "r"(a[1]), "r"(a[2]), "r"(a[3]),
          "r"(b[nf].x), "r"(b[nf].y));
    }
  }

#pragma unroll
  for (int nf = 0; nf < 16; nf++) {
    int col = nf * 8 + (lane & 3) * 2;
    if (ok0)
      *(float2*)&g_h[(size_t)r0 * D_H + col] = make_float2(acc[nf][0], acc[nf][1]);
    if (ok1)
      *(float2*)&g_h[(size_t)r1 * D_H + col] = make_float2(acc[nf][2], acc[nf][3]);
  }
}

// 8 edges per warp; edge dropout fused (lanes 0-7 hash, shfl to all)
#define EPW 8
__global__ void spmm_kernel(const int* __restrict__ aidx,
                            const float* __restrict__ adj_vals,
                            float* __restrict__ out,
                            unsigned ke0, unsigned ke1) {
  int w = (blockIdx.x * blockDim.x + threadIdx.x) >> 5;
  int lane = threadIdx.x & 31;
  int e0 = w * EPW;
  if (e0 >= N_EDGES) return;

  float vv = 0.0f;
  int el = e0 + lane;
  if (lane < EPW && el < N_EDGES) {
    unsigned b = rbits32(ke0, ke1, (unsigned)el);
    vv = (u01(b) < 0.6f) ? (adj_vals[el] / 0.6f) : 0.0f;
  }

  float4 m[EPW];
  int row[EPW];
  bool act[EPW];
#pragma unroll
  for (int i = 0; i < EPW; i++) {
    int e = e0 + i;
    float v = __shfl_sync(0xffffffffu, vv, i);
    act[i] = false;
    if (e < N_EDGES && v != 0.0f) {
      int r = aidx[e];
      int c = aidx[N_EDGES + e];
      if ((unsigned)r < (unsigned)N_NODES && (unsigned)c < (unsigned)N_NODES) {
        float4 t = *((const float4*)(g_h + (size_t)c * D_H) + lane);
        m[i] = make_float4(t.x * v, t.y * v, t.z * v, t.w * v);
        row[i] = r;
        act[i] = true;
      }
    }
  }
#pragma unroll
  for (int i = 0; i < EPW; i++)
    if (act[i])
      atomicAdd(((float4*)(out + (size_t)row[i] * D_H)) + lane, m[i]);
}

__device__ __forceinline__ float elu_f(float a) {
  return a > 0.0f ? a : expm1f(a);
}

__global__ void stats_kernel(const float* __restrict__ agg) {
  int c = threadIdx.x & (D_H - 1);
  int r0 = blockIdx.x * 2 + (threadIdx.x >> 7);
  int stride = gridDim.x * 2;
  float s = 0.0f, s2 = 0.0f;
  for (int r = r0; r < N_NODES; r += stride) {
    float f = elu_f(agg[(size_t)r * D_H + c]);
    s += f;
    s2 = fmaf(f, f, s2);
  }
  atomicAdd(&g_sum[c], (double)s);
  atomicAdd(&g_sumsq[c], (double)s2);
}

__global__ void finalize_params_kernel(const float* __restrict__ gamma,
                                       const float* __restrict__ beta) {
  int c = threadIdx.x;
  float mean = (float)(g_sum[c]   * (1.0 / (double)N_NODES));
  float ex2  = (float)(g_sumsq[c] * (1.0 / (double)N_NODES));
  float var  = ex2 - mean * mean;
  float rs = rsqrtf(var + 1e-5f);
  float sc = gamma[c] * rs;
  g_scale[c] = sc;
  g_shift[c] = fmaf(-mean, sc, beta[c]);
}

__global__ void bn_apply_kernel(float* __restrict__ out) {
  int t = blockIdx.x * blockDim.x + threadIdx.x;
  if (t >= NH / 4) return;
  float4 a = ((float4*)out)[t];
  int c = (t * 4) & (D_H - 1);
  a.x = fmaf(elu_f(a.x), g_scale[c + 0], g_shift[c + 0]);
  a.y = fmaf(elu_f(a.y), g_scale[c + 1], g_shift[c + 1]);
  a.z = fmaf(elu_f(a.z), g_scale[c + 2], g_shift[c + 2]);
  a.w = fmaf(elu_f(a.w), g_scale[c + 3], g_shift[c + 3]);
  ((float4*)out)[t] = a;
}

extern "C" void kernel_launch(void* const* d_in, const int* in_sizes, int n_in,
                              void* d_out, int out_size) {
  const float* data  = (const float*)d_in[0];
  const int*   aidx  = (const int*)d_in[1];     // int32 [2, E]
  const float* avals = (const float*)d_in[2];
  const float* W     = (const float*)d_in[3];
  const float* gamma = (const float*)d_in[4];
  const float* beta  = (const float*)d_in[5];
  float* out = (float*)d_out;

  unsigned keys[4][2];
  for (unsigned j = 0; j < 4; j++) {
    unsigned x0 = 0u, x1 = j;
    tf2x32(0u, 42u, x0, x1);
    keys[j][0] = x0; keys[j][1] = x1;
  }

  cudaMemsetAsync(out, 0, (size_t)NH * sizeof(float), 0);
  zero_stats_kernel<<<1, D_H>>>();
  wprep_kernel<<<(64 * 16 * 32 + 255) / 256, 256>>>(W);
  gemm_rng_kernel<<<(N_NODES + 127) / 128, 256>>>(data,
      keys[0][0], keys[0][1], keys[1][0], keys[1][1], keys[2][0], keys[2][1]);
  {
    int warps = (N_EDGES + EPW - 1) / EPW;
    spmm_kernel<<<(warps * 32 + 255) / 256, 256>>>(aidx, avals, out,
                                                   keys[3][0], keys[3][1]);
  }
  stats_kernel<<<592, 256>>>(out);
  finalize_params_kernel<<<1, D_H>>>(gamma, beta);
  bn_apply_kernel<<<(NH / 4 + 255) / 256, 256>>>(out);
}